// round 6
// baseline (speedup 1.0000x reference)
#include <cuda_runtime.h>
#include <cstdint>

// Problem dims (fixed by dataset)
constexpr int Bb = 4;      // batch
constexpr int Nq = 4096;   // H*W
constexpr int C  = 256;    // channels
constexpr int CK = 32;     // key/query channels

// Scratch in __device__ globals (allocation-free rule)
__device__ float g_f[(size_t)Bb * Nq * CK];              // keys
__device__ float g_g[(size_t)Bb * Nq * CK];              // queries
__device__ float g_hT[(size_t)Bb * C * Nq];              // values, transposed, tf32-pre-rounded
__device__ float g_s[(size_t)Bb * Nq * Nq];              // raw scores (256 MB)

__device__ __forceinline__ uint32_t smem_u32(const void* p) {
    return (uint32_t)__cvta_generic_to_shared(p);
}
__device__ __forceinline__ void cp16(uint32_t s, const void* g) {
    asm volatile("cp.async.cg.shared.global [%0], [%1], 16;" :: "r"(s), "l"(g));
}
__device__ __forceinline__ void cp_commit() {
    asm volatile("cp.async.commit_group;" ::: "memory");
}
__device__ __forceinline__ uint32_t f2tf32(float f) {
    uint32_t u;
    asm("cvt.rna.tf32.f32 %0, %1;" : "=r"(u) : "f"(f));
    return u;
}
__device__ __forceinline__ void mma_tf32(float* d, const uint32_t* a, const uint32_t* bfr) {
    asm volatile(
        "mma.sync.aligned.m16n8k8.row.col.f32.tf32.tf32.f32 "
        "{%0,%1,%2,%3}, {%4,%5,%6,%7}, {%8,%9}, {%0,%1,%2,%3};"
        : "+f"(d[0]), "+f"(d[1]), "+f"(d[2]), "+f"(d[3])
        : "r"(a[0]), "r"(a[1]), "r"(a[2]), "r"(a[3]), "r"(bfr[0]), "r"(bfr[1]));
}

// ===========================================================================
// Kernel 1: fused projections  [f | g | h] = x @ [Wf | Wg | Wh] + [bf|bg|bh]
// 3x tf32 mma.sync hi/lo split (fp32-grade). CTA: 128 rows x 320 cols, K=256.
// 256 threads, 8 warps (2m x 4n), warp tile 64 x 80 (10 n8-tiles).
// f,g stored fp32 row-major; h stored TRANSPOSED + tf32-rounded into g_hT.
// ===========================================================================
constexpr int PJ_NW   = 320;
constexpr int PJ_XROW = 36;
constexpr int PJ_SMEM = (128 * PJ_XROW + PJ_NW * PJ_XROW) * 4;   // 64,512 B

__global__ __launch_bounds__(256)
void proj_kernel(const float* __restrict__ x,
                 const float* __restrict__ Wf, const float* __restrict__ bfv,
                 const float* __restrict__ Wg, const float* __restrict__ bgv,
                 const float* __restrict__ Wh, const float* __restrict__ bhv) {
    extern __shared__ float sm[];
    float* Xs = sm;                       // [128][36]
    float* Ws = sm + 128 * PJ_XROW;       // [320][36]  (n-major, k-contig)

    const int t = threadIdx.x;
    const int lane = t & 31, wid = t >> 5;
    const int wm = wid >> 2, wn = wid & 3;        // 2(M) x 4(N)
    const int rowbase = blockIdx.x * 128;

    float acc[4][10][4] = {};

    for (int ch = 0; ch < 8; ch++) {
        const int k0 = ch * 32;
        __syncthreads();
        // X chunk: 128 x 32 natural layout
        #pragma unroll
        for (int i = 0; i < 4; i++) {
            int idx = t + i * 256;
            int r = idx >> 3, c4 = (idx & 7) * 4;
            *(float4*)(Xs + r * PJ_XROW + c4) =
                *(const float4*)(x + (size_t)(rowbase + r) * C + k0 + c4);
        }
        // W chunk: 32 x 320, transposed into Ws[n][k]
        #pragma unroll
        for (int i = 0; i < 10; i++) {
            int idx = t + i * 256;
            int k = idx / 80, nf4 = idx % 80;
            int n4 = nf4 * 4;
            float4 v;
            if (n4 < 32)        v = *(const float4*)(Wf + (size_t)(k0 + k) * CK + n4);
            else if (n4 < 64)   v = *(const float4*)(Wg + (size_t)(k0 + k) * CK + (n4 - 32));
            else                v = *(const float4*)(Wh + (size_t)(k0 + k) * C + (n4 - 64));
            Ws[(n4 + 0) * PJ_XROW + k] = v.x;
            Ws[(n4 + 1) * PJ_XROW + k] = v.y;
            Ws[(n4 + 2) * PJ_XROW + k] = v.z;
            Ws[(n4 + 3) * PJ_XROW + k] = v.w;
        }
        __syncthreads();

        #pragma unroll
        for (int ks = 0; ks < 4; ks++) {
            const int cc = ks * 8 + (lane & 3);
            uint32_t ah[4][4], al[4][4];
            #pragma unroll
            for (int mt = 0; mt < 4; mt++) {
                int r0 = (wm * 64 + mt * 16 + (lane >> 2)) * PJ_XROW;
                float v0 = Xs[r0 + cc],                 v1 = Xs[r0 + 8 * PJ_XROW + cc];
                float v2 = Xs[r0 + cc + 4],             v3 = Xs[r0 + 8 * PJ_XROW + cc + 4];
                ah[mt][0] = f2tf32(v0); al[mt][0] = f2tf32(v0 - __uint_as_float(ah[mt][0]));
                ah[mt][1] = f2tf32(v1); al[mt][1] = f2tf32(v1 - __uint_as_float(ah[mt][1]));
                ah[mt][2] = f2tf32(v2); al[mt][2] = f2tf32(v2 - __uint_as_float(ah[mt][2]));
                ah[mt][3] = f2tf32(v3); al[mt][3] = f2tf32(v3 - __uint_as_float(ah[mt][3]));
            }
            #pragma unroll
            for (int nt = 0; nt < 10; nt++) {
                int rn = (wn * 80 + nt * 8 + (lane >> 2)) * PJ_XROW;
                float w0 = Ws[rn + cc], w1 = Ws[rn + cc + 4];
                uint32_t bh[2], bl[2];
                bh[0] = f2tf32(w0); bl[0] = f2tf32(w0 - __uint_as_float(bh[0]));
                bh[1] = f2tf32(w1); bl[1] = f2tf32(w1 - __uint_as_float(bh[1]));
                #pragma unroll
                for (int mt = 0; mt < 4; mt++) {
                    mma_tf32(acc[mt][nt], ah[mt], bh);
                    mma_tf32(acc[mt][nt], ah[mt], bl);
                    mma_tf32(acc[mt][nt], al[mt], bh);
                }
            }
        }
    }

    // epilogue: region is warp-uniform per nt (tiles of 8 never straddle 32/64)
    #pragma unroll
    for (int nt = 0; nt < 10; nt++) {
        const int c0 = wn * 80 + nt * 8 + 2 * (lane & 3);
        #pragma unroll
        for (int mt = 0; mt < 4; mt++) {
            const int r0 = rowbase + wm * 64 + mt * 16 + (lane >> 2);
            #pragma unroll
            for (int h = 0; h < 2; h++) {
                const int r = r0 + h * 8;
                const float d0 = acc[mt][nt][h * 2 + 0];
                const float d1 = acc[mt][nt][h * 2 + 1];
                if (c0 < 32) {
                    float2 o; o.x = d0 + bfv[c0]; o.y = d1 + bfv[c0 + 1];
                    *(float2*)(g_f + (size_t)r * CK + c0) = o;
                } else if (c0 < 64) {
                    int c = c0 - 32;
                    float2 o; o.x = d0 + bgv[c]; o.y = d1 + bgv[c + 1];
                    *(float2*)(g_g + (size_t)r * CK + c) = o;
                } else {
                    int c = c0 - 64;
                    int bb = r >> 12, n = r & 4095;
                    g_hT[((size_t)bb * C + c) * Nq + n] =
                        __uint_as_float(f2tf32(d0 + bhv[c]));
                    g_hT[((size_t)bb * C + c + 1) * Nq + n] =
                        __uint_as_float(f2tf32(d1 + bhv[c + 1]));
                }
            }
        }
    }
}

// ===========================================================================
// Kernel 2: scores via 3x tf32 mma.sync (hi/lo split) -> fp32-grade logits.
// ===========================================================================
__global__ __launch_bounds__(256)
void score_kernel() {
    __shared__ float Gs[128][36];
    __shared__ float Fs[128][36];
    const int t = threadIdx.x;
    const int lane = t & 31, wid = t >> 5;
    const int wm = wid >> 2, wn = wid & 3;
    const int mbase = blockIdx.y * 128, nbase = blockIdx.x * 128;
    const size_t zoff = (size_t)blockIdx.z * Nq * CK;

    #pragma unroll
    for (int i = 0; i < 4; i++) {
        int idx = t + i * 256;
        int r = idx >> 3, c4 = (idx & 7) * 4;
        *(float4*)&Gs[r][c4] = *(const float4*)(g_g + zoff + (size_t)(mbase + r) * CK + c4);
        *(float4*)&Fs[r][c4] = *(const float4*)(g_f + zoff + (size_t)(nbase + r) * CK + c4);
    }
    __syncthreads();

    float acc[4][4][4] = {};
    #pragma unroll
    for (int ks = 0; ks < 4; ks++) {
        const int cc = ks * 8 + (lane & 3);
        uint32_t ah[4][4], al[4][4];
        #pragma unroll
        for (int mt = 0; mt < 4; mt++) {
            int r0 = wm * 64 + mt * 16 + (lane >> 2);
            float v0 = Gs[r0][cc],     v1 = Gs[r0 + 8][cc];
            float v2 = Gs[r0][cc + 4], v3 = Gs[r0 + 8][cc + 4];
            ah[mt][0] = f2tf32(v0); al[mt][0] = f2tf32(v0 - __uint_as_float(ah[mt][0]));
            ah[mt][1] = f2tf32(v1); al[mt][1] = f2tf32(v1 - __uint_as_float(ah[mt][1]));
            ah[mt][2] = f2tf32(v2); al[mt][2] = f2tf32(v2 - __uint_as_float(ah[mt][2]));
            ah[mt][3] = f2tf32(v3); al[mt][3] = f2tf32(v3 - __uint_as_float(ah[mt][3]));
        }
        #pragma unroll
        for (int nt = 0; nt < 4; nt++) {
            int rn = wn * 32 + nt * 8 + (lane >> 2);
            float w0 = Fs[rn][cc], w1 = Fs[rn][cc + 4];
            uint32_t bh[2], bl[2];
            bh[0] = f2tf32(w0); bl[0] = f2tf32(w0 - __uint_as_float(bh[0]));
            bh[1] = f2tf32(w1); bl[1] = f2tf32(w1 - __uint_as_float(bh[1]));
            #pragma unroll
            for (int mt = 0; mt < 4; mt++) {
                mma_tf32(acc[mt][nt], ah[mt], bh);
                mma_tf32(acc[mt][nt], ah[mt], bl);
                mma_tf32(acc[mt][nt], al[mt], bh);
            }
        }
    }

    float* sout = g_s + (size_t)blockIdx.z * Nq * Nq;
    #pragma unroll
    for (int mt = 0; mt < 4; mt++) {
        int r0 = mbase + wm * 64 + mt * 16 + (lane >> 2);
        #pragma unroll
        for (int nt = 0; nt < 4; nt++) {
            int col = nbase + wn * 32 + nt * 8 + 2 * (lane & 3);
            float2 o0; o0.x = acc[mt][nt][0]; o0.y = acc[mt][nt][1];
            *(float2*)(sout + (size_t)r0 * Nq + col) = o0;
            float2 o1; o1.x = acc[mt][nt][2]; o1.y = acc[mt][nt][3];
            *(float2*)(sout + (size_t)(r0 + 8) * Nq + col) = o1;
        }
    }
}

// ===========================================================================
// Kernel 3: fused exp-softmax + PV + residual.  512 threads, 16 warps (2m x 8n).
//   A (exp(P)) stored in column-PAIRED permuted layout: chunk col c = ks*8+j
//   lives at ks*8 + (j&3)*2 + (j>>2)  ->  fragment loads are LDS.64.
// ===========================================================================
constexpr int PV_AROW = 36;                        // 32 + 4 pad
constexpr int PV_AST  = 128 * PV_AROW;
constexpr int PV_BST  = 256 * PV_AROW;
constexpr int PV_SMEM = (3 * PV_AST + 4 * PV_BST + 128) * 4;   // 203,776 B
constexpr int NCH = Nq / 32;                       // 128

__global__ __launch_bounds__(512, 1)
void pv_kernel(const float* __restrict__ gamma_p,
               const float* __restrict__ x, float* __restrict__ y) {
    extern __shared__ float sm[];
    float* Abuf = sm;
    float* Bbuf = sm + 3 * PV_AST;
    float* zsm  = sm + 3 * PV_AST + 4 * PV_BST;

    const int t = threadIdx.x;
    const int lane = t & 31, wid = t >> 5;
    const int wm = wid >> 3, wn = wid & 7;         // 2(M) x 8(N)
    const int qbase = blockIdx.x * 128;
    const int b = blockIdx.y;
    const float* Pm  = g_s  + (size_t)b * Nq * Nq;
    const float* hTb = g_hT + (size_t)b * C * Nq;

    if (t < 128) zsm[t] = 0.f;

    const int tr  = t >> 3;          // 0..63
    const int tc4 = (t & 7) * 4;
    // permuted A store base offset within a 32-col chunk row
    const int apos = (tc4 >> 3) * 8 + ((tc4 & 4) >> 2);

    float4 va[2], vb[2];
    float zp[2] = {0.f, 0.f};

    auto ldgA = [&](int chunk, float4* v) {
        const float* base = Pm + (size_t)(qbase + tr) * Nq + chunk * 32 + tc4;
        v[0] = *(const float4*)(base);
        v[1] = *(const float4*)(base + (size_t)64 * Nq);
    };
    auto expSts = [&](int chunk, const float4* v) {
        float* Ad = Abuf + (chunk % 3) * PV_AST;
        #pragma unroll
        for (int i = 0; i < 2; i++) {
            float4 p;
            p.x = __uint_as_float(f2tf32(__expf(v[i].x)));
            p.y = __uint_as_float(f2tf32(__expf(v[i].y)));
            p.z = __uint_as_float(f2tf32(__expf(v[i].z)));
            p.w = __uint_as_float(f2tf32(__expf(v[i].w)));
            zp[i] += (p.x + p.y) + (p.z + p.w);
            float* d = Ad + (tr + 64 * i) * PV_AROW + apos;
            d[0] = p.x; d[2] = p.y; d[4] = p.z; d[6] = p.w;
        }
    };
    auto cpB = [&](int chunk) {
        float* Bd = Bbuf + (chunk & 3) * PV_BST;
        #pragma unroll
        for (int i = 0; i < 4; i++) {
            int idx = t + i * 512;
            int r = idx >> 3, c4 = (idx & 7) * 4;
            cp16(smem_u32(Bd + r * PV_AROW + c4),
                 hTb + (size_t)r * Nq + chunk * 32 + c4);
        }
        cp_commit();
    };

    // prologue
    cpB(0); cpB(1); cpB(2);
    ldgA(0, va);
    expSts(0, va);
    ldgA(1, va);

    float acc[4][4][4] = {};   // warp tile 64(M) x 32(N)

    for (int c = 0; c < NCH; c++) {
        if (c + 1 < NCH) expSts(c + 1, va);
        if (c + 2 < NCH) ldgA(c + 2, vb);

        int pend = NCH - 1 - c;
        if (pend >= 2)      asm volatile("cp.async.wait_group 2;" ::: "memory");
        else if (pend == 1) asm volatile("cp.async.wait_group 1;" ::: "memory");
        else                asm volatile("cp.async.wait_group 0;" ::: "memory");
        __syncthreads();

        if (c + 3 < NCH) cpB(c + 3);

        const float* Asb = Abuf + (c % 3) * PV_AST;
        const float* Bsb = Bbuf + (c & 3) * PV_BST;
        #pragma unroll
        for (int ks = 0; ks < 4; ks++) {
            const int cc  = ks * 8 + (lane & 3);          // B (natural layout)
            const int cpr = ks * 8 + (lane & 3) * 2;      // A (paired layout)
            uint32_t af[4][4];
            #pragma unroll
            for (int mt = 0; mt < 4; mt++) {
                int r0 = (wm * 64 + mt * 16 + (lane >> 2)) * PV_AROW;
                uint2 p0 = *(const uint2*)(Asb + r0 + cpr);
                uint2 p1 = *(const uint2*)(Asb + r0 + 8 * PV_AROW + cpr);
                af[mt][0] = p0.x; af[mt][2] = p0.y;
                af[mt][1] = p1.x; af[mt][3] = p1.y;
            }
            #pragma unroll
            for (int nt = 0; nt < 4; nt++) {
                int rn = (wn * 32 + nt * 8 + (lane >> 2)) * PV_AROW;
                uint32_t bf[2];
                bf[0] = __float_as_uint(Bsb[rn + cc]);
                bf[1] = __float_as_uint(Bsb[rn + cc + 4]);
                #pragma unroll
                for (int mt = 0; mt < 4; mt++)
                    mma_tf32(acc[mt][nt], af[mt], bf);
            }
        }

        va[0] = vb[0]; va[1] = vb[1];
    }

    // Z reduction
    __syncthreads();
    atomicAdd(&zsm[tr], zp[0]);
    atomicAdd(&zsm[tr + 64], zp[1]);
    __syncthreads();

    const float gam = __ldg(gamma_p);
    #pragma unroll
    for (int mt = 0; mt < 4; mt++) {
        int row0 = wm * 64 + mt * 16 + (lane >> 2);
        float sc0 = gam / zsm[row0];
        float sc1 = gam / zsm[row0 + 8];
        #pragma unroll
        for (int nt = 0; nt < 4; nt++) {
            int col = wn * 32 + nt * 8 + 2 * (lane & 3);
            size_t base = ((size_t)b * Nq + qbase + row0) * C + col;
            float2 x0 = *(const float2*)(x + base);
            float2 o0;
            o0.x = sc0 * acc[mt][nt][0] + x0.x;
            o0.y = sc0 * acc[mt][nt][1] + x0.y;
            *(float2*)(y + base) = o0;
            size_t base2 = base + 8 * (size_t)C;
            float2 x1 = *(const float2*)(x + base2);
            float2 o1;
            o1.x = sc1 * acc[mt][nt][2] + x1.x;
            o1.y = sc1 * acc[mt][nt][3] + x1.y;
            *(float2*)(y + base2) = o1;
        }
    }
}

// ===========================================================================
extern "C" void kernel_launch(void* const* d_in, const int* in_sizes, int n_in,
                              void* d_out, int out_size) {
    (void)in_sizes; (void)n_in; (void)out_size;
    const float* x     = (const float*)d_in[0];
    const float* Wf    = (const float*)d_in[1];
    const float* bf    = (const float*)d_in[2];
    const float* Wg    = (const float*)d_in[3];
    const float* bg    = (const float*)d_in[4];
    const float* Wh    = (const float*)d_in[5];
    const float* bh    = (const float*)d_in[6];
    const float* gamma = (const float*)d_in[7];
    float* y = (float*)d_out;

    cudaFuncSetAttribute(proj_kernel, cudaFuncAttributeMaxDynamicSharedMemorySize, PJ_SMEM);
    cudaFuncSetAttribute(pv_kernel, cudaFuncAttributeMaxDynamicSharedMemorySize, PV_SMEM);

    proj_kernel<<<(Bb * Nq) / 128, 256, PJ_SMEM>>>(x, Wf, bf, Wg, bg, Wh, bh);
    score_kernel<<<dim3(Nq / 128, Nq / 128, Bb), 256>>>();
    pv_kernel<<<dim3(Nq / 128, Bb), 512, PV_SMEM>>>(gamma, x, y);
}

// round 7
// speedup vs baseline: 1.0876x; 1.0876x over previous
#include <cuda_runtime.h>
#include <cstdint>

// Problem dims (fixed by dataset)
constexpr int Bb = 4;      // batch
constexpr int Nq = 4096;   // H*W
constexpr int C  = 256;    // channels
constexpr int CK = 32;     // key/query channels

// Scratch in __device__ globals (allocation-free rule)
__device__ float g_f[(size_t)Bb * Nq * CK];              // keys
__device__ float g_g[(size_t)Bb * Nq * CK];              // queries
__device__ float g_hT[(size_t)Bb * C * Nq];              // values, transposed, tf32-pre-rounded
__device__ float g_s[(size_t)Bb * Nq * Nq];              // raw scores (256 MB)

__device__ __forceinline__ uint32_t smem_u32(const void* p) {
    return (uint32_t)__cvta_generic_to_shared(p);
}
__device__ __forceinline__ void cp16(uint32_t s, const void* g) {
    asm volatile("cp.async.cg.shared.global [%0], [%1], 16;" :: "r"(s), "l"(g));
}
__device__ __forceinline__ void cp_commit() {
    asm volatile("cp.async.commit_group;" ::: "memory");
}
__device__ __forceinline__ uint32_t f2tf32(float f) {
    uint32_t u;
    asm("cvt.rna.tf32.f32 %0, %1;" : "=r"(u) : "f"(f));
    return u;
}
__device__ __forceinline__ void mma_tf32(float* d, const uint32_t* a, const uint32_t* bfr) {
    asm volatile(
        "mma.sync.aligned.m16n8k8.row.col.f32.tf32.tf32.f32 "
        "{%0,%1,%2,%3}, {%4,%5,%6,%7}, {%8,%9}, {%0,%1,%2,%3};"
        : "+f"(d[0]), "+f"(d[1]), "+f"(d[2]), "+f"(d[3])
        : "r"(a[0]), "r"(a[1]), "r"(a[2]), "r"(a[3]), "r"(bfr[0]), "r"(bfr[1]));
}

// ===========================================================================
// Kernel 1: fused projections  [f | g | h] = x @ [Wf | Wg | Wh] + [bf|bg|bh]
// f,g (cols 0..63): 3x tf32 hi/lo split (fp32-grade, they feed logits).
// h   (cols 64..319): single-pass tf32 (feeds tf32 PV anyway).
// CTA: 64 rows x 320 cols, K=256. 256 threads, 8 warps (2m x 4n),
// warp tile 32 x 80. 2 CTAs/SM.
// f,g stored fp32 row-major; h stored TRANSPOSED + tf32-rounded into g_hT.
// ===========================================================================
constexpr int PJ_XROW = 36;
constexpr int PJ_SMEM = (64 * PJ_XROW + 320 * PJ_XROW) * 4;   // 55,296 B

__global__ __launch_bounds__(256, 2)
void proj_kernel(const float* __restrict__ x,
                 const float* __restrict__ Wf, const float* __restrict__ bfv,
                 const float* __restrict__ Wg, const float* __restrict__ bgv,
                 const float* __restrict__ Wh, const float* __restrict__ bhv) {
    extern __shared__ float sm[];
    float* Xs = sm;                       // [64][36]
    float* Ws = sm + 64 * PJ_XROW;        // [320][36]  (n-major, k-contig)

    const int t = threadIdx.x;
    const int lane = t & 31, wid = t >> 5;
    const int wm = wid >> 2, wn = wid & 3;        // 2(M) x 4(N)
    const int rowbase = blockIdx.x * 64;

    float acc[2][10][4] = {};

    for (int ch = 0; ch < 8; ch++) {
        const int k0 = ch * 32;
        __syncthreads();
        // X chunk: 64 x 32 natural layout (512 float4, 2/thread)
        #pragma unroll
        for (int i = 0; i < 2; i++) {
            int idx = t + i * 256;
            int r = idx >> 3, c4 = (idx & 7) * 4;
            *(float4*)(Xs + r * PJ_XROW + c4) =
                *(const float4*)(x + (size_t)(rowbase + r) * C + k0 + c4);
        }
        // W chunk: 32 x 320, transposed into Ws[n][k]
        #pragma unroll
        for (int i = 0; i < 10; i++) {
            int idx = t + i * 256;
            int k = idx / 80, nf4 = idx % 80;
            int n4 = nf4 * 4;
            float4 v;
            if (n4 < 32)        v = *(const float4*)(Wf + (size_t)(k0 + k) * CK + n4);
            else if (n4 < 64)   v = *(const float4*)(Wg + (size_t)(k0 + k) * CK + (n4 - 32));
            else                v = *(const float4*)(Wh + (size_t)(k0 + k) * C + (n4 - 64));
            Ws[(n4 + 0) * PJ_XROW + k] = v.x;
            Ws[(n4 + 1) * PJ_XROW + k] = v.y;
            Ws[(n4 + 2) * PJ_XROW + k] = v.z;
            Ws[(n4 + 3) * PJ_XROW + k] = v.w;
        }
        __syncthreads();

        #pragma unroll
        for (int ks = 0; ks < 4; ks++) {
            const int cc = ks * 8 + (lane & 3);
            uint32_t ah[2][4], al[2][4];
            #pragma unroll
            for (int mt = 0; mt < 2; mt++) {
                int r0 = (wm * 32 + mt * 16 + (lane >> 2)) * PJ_XROW;
                float v0 = Xs[r0 + cc],     v1 = Xs[r0 + 8 * PJ_XROW + cc];
                float v2 = Xs[r0 + cc + 4], v3 = Xs[r0 + 8 * PJ_XROW + cc + 4];
                ah[mt][0] = f2tf32(v0); al[mt][0] = f2tf32(v0 - __uint_as_float(ah[mt][0]));
                ah[mt][1] = f2tf32(v1); al[mt][1] = f2tf32(v1 - __uint_as_float(ah[mt][1]));
                ah[mt][2] = f2tf32(v2); al[mt][2] = f2tf32(v2 - __uint_as_float(ah[mt][2]));
                ah[mt][3] = f2tf32(v3); al[mt][3] = f2tf32(v3 - __uint_as_float(ah[mt][3]));
            }
            #pragma unroll
            for (int nt = 0; nt < 10; nt++) {
                const int c0 = wn * 80 + nt * 8;       // compile-time per (wn,nt)
                int rn = (c0 + (lane >> 2)) * PJ_XROW;
                float w0 = Ws[rn + cc], w1 = Ws[rn + cc + 4];
                uint32_t bh[2];
                bh[0] = f2tf32(w0); bh[1] = f2tf32(w1);
                if (c0 < 64) {
                    uint32_t bl[2];
                    bl[0] = f2tf32(w0 - __uint_as_float(bh[0]));
                    bl[1] = f2tf32(w1 - __uint_as_float(bh[1]));
                    #pragma unroll
                    for (int mt = 0; mt < 2; mt++) {
                        mma_tf32(acc[mt][nt], ah[mt], bh);
                        mma_tf32(acc[mt][nt], ah[mt], bl);
                        mma_tf32(acc[mt][nt], al[mt], bh);
                    }
                } else {
                    #pragma unroll
                    for (int mt = 0; mt < 2; mt++)
                        mma_tf32(acc[mt][nt], ah[mt], bh);
                }
            }
        }
    }

    // epilogue (branch uniform per (wn,nt): 8-wide tiles never straddle 32/64)
    #pragma unroll
    for (int nt = 0; nt < 10; nt++) {
        const int c0 = wn * 80 + nt * 8 + 2 * (lane & 3);
        #pragma unroll
        for (int mt = 0; mt < 2; mt++) {
            const int r0 = rowbase + wm * 32 + mt * 16 + (lane >> 2);
            #pragma unroll
            for (int h = 0; h < 2; h++) {
                const int r = r0 + h * 8;
                const float d0 = acc[mt][nt][h * 2 + 0];
                const float d1 = acc[mt][nt][h * 2 + 1];
                if (c0 < 32) {
                    float2 o; o.x = d0 + bfv[c0]; o.y = d1 + bfv[c0 + 1];
                    *(float2*)(g_f + (size_t)r * CK + c0) = o;
                } else if (c0 < 64) {
                    int c = c0 - 32;
                    float2 o; o.x = d0 + bgv[c]; o.y = d1 + bgv[c + 1];
                    *(float2*)(g_g + (size_t)r * CK + c) = o;
                } else {
                    int c = c0 - 64;
                    int bb = r >> 12, n = r & 4095;
                    g_hT[((size_t)bb * C + c) * Nq + n] =
                        __uint_as_float(f2tf32(d0 + bhv[c]));
                    g_hT[((size_t)bb * C + c + 1) * Nq + n] =
                        __uint_as_float(f2tf32(d1 + bhv[c + 1]));
                }
            }
        }
    }
}

// ===========================================================================
// Kernel 2: scores via 3x tf32 mma.sync (hi/lo split) -> fp32-grade logits.
// ===========================================================================
__global__ __launch_bounds__(256)
void score_kernel() {
    __shared__ float Gs[128][36];
    __shared__ float Fs[128][36];
    const int t = threadIdx.x;
    const int lane = t & 31, wid = t >> 5;
    const int wm = wid >> 2, wn = wid & 3;
    const int mbase = blockIdx.y * 128, nbase = blockIdx.x * 128;
    const size_t zoff = (size_t)blockIdx.z * Nq * CK;

    #pragma unroll
    for (int i = 0; i < 4; i++) {
        int idx = t + i * 256;
        int r = idx >> 3, c4 = (idx & 7) * 4;
        *(float4*)&Gs[r][c4] = *(const float4*)(g_g + zoff + (size_t)(mbase + r) * CK + c4);
        *(float4*)&Fs[r][c4] = *(const float4*)(g_f + zoff + (size_t)(nbase + r) * CK + c4);
    }
    __syncthreads();

    float acc[4][4][4] = {};
    #pragma unroll
    for (int ks = 0; ks < 4; ks++) {
        const int cc = ks * 8 + (lane & 3);
        uint32_t ah[4][4], al[4][4];
        #pragma unroll
        for (int mt = 0; mt < 4; mt++) {
            int r0 = wm * 64 + mt * 16 + (lane >> 2);
            float v0 = Gs[r0][cc],     v1 = Gs[r0 + 8][cc];
            float v2 = Gs[r0][cc + 4], v3 = Gs[r0 + 8][cc + 4];
            ah[mt][0] = f2tf32(v0); al[mt][0] = f2tf32(v0 - __uint_as_float(ah[mt][0]));
            ah[mt][1] = f2tf32(v1); al[mt][1] = f2tf32(v1 - __uint_as_float(ah[mt][1]));
            ah[mt][2] = f2tf32(v2); al[mt][2] = f2tf32(v2 - __uint_as_float(ah[mt][2]));
            ah[mt][3] = f2tf32(v3); al[mt][3] = f2tf32(v3 - __uint_as_float(ah[mt][3]));
        }
        #pragma unroll
        for (int nt = 0; nt < 4; nt++) {
            int rn = wn * 32 + nt * 8 + (lane >> 2);
            float w0 = Fs[rn][cc], w1 = Fs[rn][cc + 4];
            uint32_t bh[2], bl[2];
            bh[0] = f2tf32(w0); bl[0] = f2tf32(w0 - __uint_as_float(bh[0]));
            bh[1] = f2tf32(w1); bl[1] = f2tf32(w1 - __uint_as_float(bh[1]));
            #pragma unroll
            for (int mt = 0; mt < 4; mt++) {
                mma_tf32(acc[mt][nt], ah[mt], bh);
                mma_tf32(acc[mt][nt], ah[mt], bl);
                mma_tf32(acc[mt][nt], al[mt], bh);
            }
        }
    }

    float* sout = g_s + (size_t)blockIdx.z * Nq * Nq;
    #pragma unroll
    for (int mt = 0; mt < 4; mt++) {
        int r0 = mbase + wm * 64 + mt * 16 + (lane >> 2);
        #pragma unroll
        for (int nt = 0; nt < 4; nt++) {
            int col = nbase + wn * 32 + nt * 8 + 2 * (lane & 3);
            float2 o0; o0.x = acc[mt][nt][0]; o0.y = acc[mt][nt][1];
            *(float2*)(sout + (size_t)r0 * Nq + col) = o0;
            float2 o1; o1.x = acc[mt][nt][2]; o1.y = acc[mt][nt][3];
            *(float2*)(sout + (size_t)(r0 + 8) * Nq + col) = o1;
        }
    }
}

// ===========================================================================
// Kernel 3: fused exp-softmax + PV + residual.  512 threads, 16 warps (2m x 8n).
//   (R5 layout: natural A rows, no pairing — that variant measured fastest.)
// ===========================================================================
constexpr int PV_AROW = 36;                        // 32 + 4 pad
constexpr int PV_AST  = 128 * PV_AROW;
constexpr int PV_BST  = 256 * PV_AROW;
constexpr int PV_SMEM = (3 * PV_AST + 4 * PV_BST + 128) * 4;   // 203,776 B
constexpr int NCH = Nq / 32;                       // 128

__global__ __launch_bounds__(512, 1)
void pv_kernel(const float* __restrict__ gamma_p,
               const float* __restrict__ x, float* __restrict__ y) {
    extern __shared__ float sm[];
    float* Abuf = sm;
    float* Bbuf = sm + 3 * PV_AST;
    float* zsm  = sm + 3 * PV_AST + 4 * PV_BST;

    const int t = threadIdx.x;
    const int lane = t & 31, wid = t >> 5;
    const int wm = wid >> 3, wn = wid & 7;         // 2(M) x 8(N)
    const int qbase = blockIdx.x * 128;
    const int b = blockIdx.y;
    const float* Pm  = g_s  + (size_t)b * Nq * Nq;
    const float* hTb = g_hT + (size_t)b * C * Nq;

    if (t < 128) zsm[t] = 0.f;

    const int tr  = t >> 3;          // 0..63
    const int tc4 = (t & 7) * 4;

    float4 va[2], vb[2];
    float zp[2] = {0.f, 0.f};

    auto ldgA = [&](int chunk, float4* v) {
        const float* base = Pm + (size_t)(qbase + tr) * Nq + chunk * 32 + tc4;
        v[0] = *(const float4*)(base);
        v[1] = *(const float4*)(base + (size_t)64 * Nq);
    };
    auto expSts = [&](int chunk, const float4* v) {
        float* Ad = Abuf + (chunk % 3) * PV_AST;
        #pragma unroll
        for (int i = 0; i < 2; i++) {
            float4 p;
            p.x = __uint_as_float(f2tf32(__expf(v[i].x)));
            p.y = __uint_as_float(f2tf32(__expf(v[i].y)));
            p.z = __uint_as_float(f2tf32(__expf(v[i].z)));
            p.w = __uint_as_float(f2tf32(__expf(v[i].w)));
            zp[i] += (p.x + p.y) + (p.z + p.w);
            *(float4*)(Ad + (tr + 64 * i) * PV_AROW + tc4) = p;
        }
    };
    auto cpB = [&](int chunk) {
        float* Bd = Bbuf + (chunk & 3) * PV_BST;
        #pragma unroll
        for (int i = 0; i < 4; i++) {
            int idx = t + i * 512;
            int r = idx >> 3, c4 = (idx & 7) * 4;
            cp16(smem_u32(Bd + r * PV_AROW + c4),
                 hTb + (size_t)r * Nq + chunk * 32 + c4);
        }
        cp_commit();
    };

    // prologue
    cpB(0); cpB(1); cpB(2);
    ldgA(0, va);
    expSts(0, va);
    ldgA(1, va);

    float acc[4][4][4] = {};   // warp tile 64(M) x 32(N)

    for (int c = 0; c < NCH; c++) {
        if (c + 1 < NCH) expSts(c + 1, va);
        if (c + 2 < NCH) ldgA(c + 2, vb);

        int pend = NCH - 1 - c;
        if (pend >= 2)      asm volatile("cp.async.wait_group 2;" ::: "memory");
        else if (pend == 1) asm volatile("cp.async.wait_group 1;" ::: "memory");
        else                asm volatile("cp.async.wait_group 0;" ::: "memory");
        __syncthreads();

        if (c + 3 < NCH) cpB(c + 3);

        const float* Asb = Abuf + (c % 3) * PV_AST;
        const float* Bsb = Bbuf + (c & 3) * PV_BST;
        #pragma unroll
        for (int ks = 0; ks < 4; ks++) {
            const int cc = ks * 8 + (lane & 3);
            uint32_t af[4][4];
            #pragma unroll
            for (int mt = 0; mt < 4; mt++) {
                int r0 = (wm * 64 + mt * 16 + (lane >> 2)) * PV_AROW;
                af[mt][0] = __float_as_uint(Asb[r0 + cc]);
                af[mt][1] = __float_as_uint(Asb[r0 + 8 * PV_AROW + cc]);
                af[mt][2] = __float_as_uint(Asb[r0 + cc + 4]);
                af[mt][3] = __float_as_uint(Asb[r0 + 8 * PV_AROW + cc + 4]);
            }
            #pragma unroll
            for (int nt = 0; nt < 4; nt++) {
                int rn = (wn * 32 + nt * 8 + (lane >> 2)) * PV_AROW;
                uint32_t bf[2];
                bf[0] = __float_as_uint(Bsb[rn + cc]);
                bf[1] = __float_as_uint(Bsb[rn + cc + 4]);
                #pragma unroll
                for (int mt = 0; mt < 4; mt++)
                    mma_tf32(acc[mt][nt], af[mt], bf);
            }
        }

        va[0] = vb[0]; va[1] = vb[1];
    }

    // Z reduction
    __syncthreads();
    atomicAdd(&zsm[tr], zp[0]);
    atomicAdd(&zsm[tr + 64], zp[1]);
    __syncthreads();

    const float gam = __ldg(gamma_p);
    #pragma unroll
    for (int mt = 0; mt < 4; mt++) {
        int row0 = wm * 64 + mt * 16 + (lane >> 2);
        float sc0 = gam / zsm[row0];
        float sc1 = gam / zsm[row0 + 8];
        #pragma unroll
        for (int nt = 0; nt < 4; nt++) {
            int col = wn * 32 + nt * 8 + 2 * (lane & 3);
            size_t base = ((size_t)b * Nq + qbase + row0) * C + col;
            float2 x0 = *(const float2*)(x + base);
            float2 o0;
            o0.x = sc0 * acc[mt][nt][0] + x0.x;
            o0.y = sc0 * acc[mt][nt][1] + x0.y;
            *(float2*)(y + base) = o0;
            size_t base2 = base + 8 * (size_t)C;
            float2 x1 = *(const float2*)(x + base2);
            float2 o1;
            o1.x = sc1 * acc[mt][nt][2] + x1.x;
            o1.y = sc1 * acc[mt][nt][3] + x1.y;
            *(float2*)(y + base2) = o1;
        }
    }
}

// ===========================================================================
extern "C" void kernel_launch(void* const* d_in, const int* in_sizes, int n_in,
                              void* d_out, int out_size) {
    (void)in_sizes; (void)n_in; (void)out_size;
    const float* x     = (const float*)d_in[0];
    const float* Wf    = (const float*)d_in[1];
    const float* bf    = (const float*)d_in[2];
    const float* Wg    = (const float*)d_in[3];
    const float* bg    = (const float*)d_in[4];
    const float* Wh    = (const float*)d_in[5];
    const float* bh    = (const float*)d_in[6];
    const float* gamma = (const float*)d_in[7];
    float* y = (float*)d_out;

    cudaFuncSetAttribute(proj_kernel, cudaFuncAttributeMaxDynamicSharedMemorySize, PJ_SMEM);
    cudaFuncSetAttribute(pv_kernel, cudaFuncAttributeMaxDynamicSharedMemorySize, PV_SMEM);

    proj_kernel<<<(Bb * Nq) / 64, 256, PJ_SMEM>>>(x, Wf, bf, Wg, bg, Wh, bh);
    score_kernel<<<dim3(Nq / 128, Nq / 128, Bb), 256>>>();
    pv_kernel<<<dim3(Nq / 128, Bb), 512, PV_SMEM>>>(gamma, x, y);
}

// round 8
// speedup vs baseline: 1.3895x; 1.2775x over previous
#include <cuda_runtime.h>
#include <cstdint>

// Problem dims (fixed by dataset)
constexpr int Bb = 4;      // batch
constexpr int Nq = 4096;   // H*W
constexpr int C  = 256;    // channels
constexpr int CK = 32;     // key/query channels

// Scratch in __device__ globals (allocation-free rule)
__device__ float g_f [(size_t)Bb * Nq * CK];             // keys   (tf32 hi)
__device__ float g_fl[(size_t)Bb * Nq * CK];             // keys   (lo residual)
__device__ float g_g [(size_t)Bb * Nq * CK];             // queries(tf32 hi)
__device__ float g_gl[(size_t)Bb * Nq * CK];             // queries(lo residual)
__device__ float g_hT[(size_t)Bb * C * Nq];              // values, transposed, tf32-rounded
__device__ float g_s [(size_t)Bb * Nq * Nq];             // raw scores (256 MB)
__device__ float g_WT  [320 * 256];                      // [Wf|Wg|Wh]^T, tf32 hi
__device__ float g_WTlo[64 * 256];                       // lo residual for f,g cols

__device__ __forceinline__ uint32_t smem_u32(const void* p) {
    return (uint32_t)__cvta_generic_to_shared(p);
}
__device__ __forceinline__ void cp16(uint32_t s, const void* g) {
    asm volatile("cp.async.cg.shared.global [%0], [%1], 16;" :: "r"(s), "l"(g));
}
__device__ __forceinline__ void cp_commit() {
    asm volatile("cp.async.commit_group;" ::: "memory");
}
__device__ __forceinline__ uint32_t f2tf32(float f) {
    uint32_t u;
    asm("cvt.rna.tf32.f32 %0, %1;" : "=r"(u) : "f"(f));
    return u;
}
__device__ __forceinline__ void mma_tf32(float* d, const uint32_t* a, const uint32_t* bfr) {
    asm volatile(
        "mma.sync.aligned.m16n8k8.row.col.f32.tf32.tf32.f32 "
        "{%0,%1,%2,%3}, {%4,%5,%6,%7}, {%8,%9}, {%0,%1,%2,%3};"
        : "+f"(d[0]), "+f"(d[1]), "+f"(d[2]), "+f"(d[3])
        : "r"(a[0]), "r"(a[1]), "r"(a[2]), "r"(a[3]), "r"(bfr[0]), "r"(bfr[1]));
}
// ldmatrix on f32 tiles: 8x4-f32 tile == 8x8-b16 tile bit-wise; lane gets
// (row=lane>>2, f32col=lane&3) which is exactly the tf32 mma fragment layout.
__device__ __forceinline__ void ldsm4(uint32_t* r, uint32_t a) {
    asm volatile("ldmatrix.sync.aligned.m8n8.x4.shared.b16 {%0,%1,%2,%3}, [%4];"
        : "=r"(r[0]), "=r"(r[1]), "=r"(r[2]), "=r"(r[3]) : "r"(a));
}
__device__ __forceinline__ void ldsm2(uint32_t* r, uint32_t a) {
    asm volatile("ldmatrix.sync.aligned.m8n8.x2.shared.b16 {%0,%1}, [%2];"
        : "=r"(r[0]), "=r"(r[1]) : "r"(a));
}

// ===========================================================================
// Kernel 0: W pre-transpose + tf32 hi/lo pre-split (one-shot, tiny)
//   g_WT[n][k] = tf32(W[k][n]),  n: 0-31 f, 32-63 g, 64-319 h
//   g_WTlo[n][k] = tf32(W - hi)  for n < 64
// ===========================================================================
__global__ void wtrans_kernel(const float* __restrict__ Wf,
                              const float* __restrict__ Wg,
                              const float* __restrict__ Wh) {
    int idx = blockIdx.x * 256 + threadIdx.x;       // 320*256 total
    int n = idx >> 8, k = idx & 255;
    float w;
    if (n < 32)       w = Wf[k * CK + n];
    else if (n < 64)  w = Wg[k * CK + (n - 32)];
    else              w = Wh[k * C + (n - 64)];
    uint32_t hi = f2tf32(w);
    g_WT[n * 256 + k] = __uint_as_float(hi);
    if (n < 64)
        g_WTlo[n * 256 + k] = __uint_as_float(f2tf32(w - __uint_as_float(hi)));
}

// ===========================================================================
// Kernel 1: fused projections via ldmatrix + tensor cores.
// CTA: 64 rows x 320 cols, K=256. 8 warps (2m x 4n), warp cols nt*32+wn*8.
// nt=0 (f), nt=1 (g): 3x hi/lo split; nt>=2 (h): single-pass tf32.
// ===========================================================================
constexpr int PJ_SMEM = (64 * 36 + 320 * 36 + 64 * 36) * 4;   // 64,512 B

__global__ __launch_bounds__(256, 2)
void proj_kernel(const float* __restrict__ x,
                 const float* __restrict__ bfv, const float* __restrict__ bgv,
                 const float* __restrict__ bhv) {
    extern __shared__ float sm[];
    float* Xs  = sm;                   // [64][36]
    float* Whs = sm + 64 * 36;         // [320][36]
    float* Wls = sm + 64 * 36 + 320 * 36;  // [64][36]

    const int t = threadIdx.x;
    const int lane = t & 31, wid = t >> 5;
    const int wm = wid >> 2, wn = wid & 3;
    const int rowbase = blockIdx.x * 64;

    const int arow = (lane & 7) + ((lane >> 3) & 1) * 8;
    const int acol = (lane >> 4) * 4;
    const int brow2 = lane & 7;
    const int bcol2 = ((lane >> 3) & 1) * 4;

    const uint32_t XsU = smem_u32(Xs), WhU = smem_u32(Whs), WlU = smem_u32(Wls);

    float acc[2][10][4] = {};

    for (int ch = 0; ch < 8; ch++) {
        const int k0 = ch * 32;
        __syncthreads();
        #pragma unroll
        for (int i = 0; i < 2; i++) {            // X: 512 f4
            int idx = t + i * 256;
            int r = idx >> 3, c4 = (idx & 7) * 4;
            cp16(XsU + (r * 36 + c4) * 4, x + (size_t)(rowbase + r) * C + k0 + c4);
        }
        #pragma unroll
        for (int i = 0; i < 10; i++) {           // W hi: 2560 f4
            int idx = t + i * 256;
            int r = idx >> 3, c4 = (idx & 7) * 4;
            cp16(WhU + (r * 36 + c4) * 4, g_WT + r * 256 + k0 + c4);
        }
        #pragma unroll
        for (int i = 0; i < 2; i++) {            // W lo: 512 f4
            int idx = t + i * 256;
            int r = idx >> 3, c4 = (idx & 7) * 4;
            cp16(WlU + (r * 36 + c4) * 4, g_WTlo + r * 256 + k0 + c4);
        }
        cp_commit();
        asm volatile("cp.async.wait_group 0;" ::: "memory");
        __syncthreads();

        #pragma unroll
        for (int ks = 0; ks < 4; ks++) {
            uint32_t xr[2][4], ah[2][4], al[2][4];
            #pragma unroll
            for (int mt = 0; mt < 2; mt++) {
                ldsm4(xr[mt], XsU + ((wm * 32 + mt * 16 + arow) * 36 + ks * 8 + acol) * 4);
                #pragma unroll
                for (int e = 0; e < 4; e++) {
                    float v = __uint_as_float(xr[mt][e]);
                    ah[mt][e] = f2tf32(v);
                    al[mt][e] = f2tf32(v - __uint_as_float(ah[mt][e]));
                }
            }
            #pragma unroll
            for (int nt = 0; nt < 10; nt++) {
                const int c0 = nt * 32 + wn * 8;
                uint32_t bh[2];
                ldsm2(bh, WhU + ((c0 + brow2) * 36 + ks * 8 + bcol2) * 4);
                if (nt < 2) {
                    uint32_t bl[2];
                    ldsm2(bl, WlU + ((c0 + brow2) * 36 + ks * 8 + bcol2) * 4);
                    #pragma unroll
                    for (int mt = 0; mt < 2; mt++) {
                        mma_tf32(acc[mt][nt], ah[mt], bh);
                        mma_tf32(acc[mt][nt], ah[mt], bl);
                        mma_tf32(acc[mt][nt], al[mt], bh);
                    }
                } else {
                    #pragma unroll
                    for (int mt = 0; mt < 2; mt++)
                        mma_tf32(acc[mt][nt], ah[mt], bh);
                }
            }
        }
    }

    // epilogue
    #pragma unroll
    for (int nt = 0; nt < 10; nt++) {
        const int c0 = nt * 32 + wn * 8 + 2 * (lane & 3);
        #pragma unroll
        for (int mt = 0; mt < 2; mt++) {
            const int r0 = rowbase + wm * 32 + mt * 16 + (lane >> 2);
            #pragma unroll
            for (int h = 0; h < 2; h++) {
                const int r = r0 + h * 8;
                const float d0 = acc[mt][nt][h * 2 + 0];
                const float d1 = acc[mt][nt][h * 2 + 1];
                if (nt == 0) {
                    float v0 = d0 + bfv[c0], v1 = d1 + bfv[c0 + 1];
                    uint32_t h0 = f2tf32(v0), h1 = f2tf32(v1);
                    float2 oh; oh.x = __uint_as_float(h0); oh.y = __uint_as_float(h1);
                    float2 ol;
                    ol.x = __uint_as_float(f2tf32(v0 - oh.x));
                    ol.y = __uint_as_float(f2tf32(v1 - oh.y));
                    *(float2*)(g_f  + (size_t)r * CK + c0) = oh;
                    *(float2*)(g_fl + (size_t)r * CK + c0) = ol;
                } else if (nt == 1) {
                    int c = c0 - 32;
                    float v0 = d0 + bgv[c], v1 = d1 + bgv[c + 1];
                    uint32_t h0 = f2tf32(v0), h1 = f2tf32(v1);
                    float2 oh; oh.x = __uint_as_float(h0); oh.y = __uint_as_float(h1);
                    float2 ol;
                    ol.x = __uint_as_float(f2tf32(v0 - oh.x));
                    ol.y = __uint_as_float(f2tf32(v1 - oh.y));
                    *(float2*)(g_g  + (size_t)r * CK + c) = oh;
                    *(float2*)(g_gl + (size_t)r * CK + c) = ol;
                } else {
                    int c = c0 - 64;
                    int bb = r >> 12, n = r & 4095;
                    g_hT[((size_t)bb * C + c) * Nq + n] =
                        __uint_as_float(f2tf32(d0 + bhv[c]));
                    g_hT[((size_t)bb * C + c + 1) * Nq + n] =
                        __uint_as_float(f2tf32(d1 + bhv[c + 1]));
                }
            }
        }
    }
}

// ===========================================================================
// Kernel 2: scores, pre-split hi/lo inputs -> pure LDSM + HMMA loop.
// ===========================================================================
constexpr int SC_SMEM = 4 * 128 * 36 * 4;   // 73,728 B

__global__ __launch_bounds__(256)
void score_kernel() {
    extern __shared__ float sm[];
    float* Gh = sm;
    float* Gl = sm + 4608;
    float* Fh = sm + 9216;
    float* Fl = sm + 13824;

    const int t = threadIdx.x;
    const int lane = t & 31, wid = t >> 5;
    const int wm = wid >> 2, wn = wid & 3;
    const int mbase = blockIdx.y * 128, nbase = blockIdx.x * 128;
    const size_t zoff = (size_t)blockIdx.z * Nq * CK;

    #pragma unroll
    for (int i = 0; i < 4; i++) {
        int idx = t + i * 256;
        int r = idx >> 3, c4 = (idx & 7) * 4;
        *(float4*)(Gh + r * 36 + c4) = *(const float4*)(g_g  + zoff + (size_t)(mbase + r) * CK + c4);
        *(float4*)(Gl + r * 36 + c4) = *(const float4*)(g_gl + zoff + (size_t)(mbase + r) * CK + c4);
        *(float4*)(Fh + r * 36 + c4) = *(const float4*)(g_f  + zoff + (size_t)(nbase + r) * CK + c4);
        *(float4*)(Fl + r * 36 + c4) = *(const float4*)(g_fl + zoff + (size_t)(nbase + r) * CK + c4);
    }
    __syncthreads();

    const int arow = (lane & 7) + ((lane >> 3) & 1) * 8;
    const int acol = (lane >> 4) * 4;
    const int brow = (lane >> 4) * 8 + (lane & 7);
    const int bcol = ((lane >> 3) & 1) * 4;
    const uint32_t GhU = smem_u32(Gh), GlU = smem_u32(Gl);
    const uint32_t FhU = smem_u32(Fh), FlU = smem_u32(Fl);

    float acc[4][4][4] = {};
    #pragma unroll
    for (int ks = 0; ks < 4; ks++) {
        uint32_t ah[4][4], al[4][4];
        #pragma unroll
        for (int mt = 0; mt < 4; mt++) {
            uint32_t off = ((wm * 64 + mt * 16 + arow) * 36 + ks * 8 + acol) * 4;
            ldsm4(ah[mt], GhU + off);
            ldsm4(al[mt], GlU + off);
        }
        #pragma unroll
        for (int j = 0; j < 2; j++) {
            uint32_t bh[4], bl[4];
            uint32_t off = ((wn * 32 + j * 16 + brow) * 36 + ks * 8 + bcol) * 4;
            ldsm4(bh, FhU + off);
            ldsm4(bl, FlU + off);
            #pragma unroll
            for (int sub = 0; sub < 2; sub++) {
                #pragma unroll
                for (int mt = 0; mt < 4; mt++) {
                    mma_tf32(acc[mt][2 * j + sub], ah[mt], bh + sub * 2);
                    mma_tf32(acc[mt][2 * j + sub], ah[mt], bl + sub * 2);
                    mma_tf32(acc[mt][2 * j + sub], al[mt], bh + sub * 2);
                }
            }
        }
    }

    float* sout = g_s + (size_t)blockIdx.z * Nq * Nq;
    #pragma unroll
    for (int mt = 0; mt < 4; mt++) {
        int r0 = mbase + wm * 64 + mt * 16 + (lane >> 2);
        #pragma unroll
        for (int nt = 0; nt < 4; nt++) {
            int col = nbase + wn * 32 + nt * 8 + 2 * (lane & 3);
            float2 o0; o0.x = acc[mt][nt][0]; o0.y = acc[mt][nt][1];
            *(float2*)(sout + (size_t)r0 * Nq + col) = o0;
            float2 o1; o1.x = acc[mt][nt][2]; o1.y = acc[mt][nt][3];
            *(float2*)(sout + (size_t)(r0 + 8) * Nq + col) = o1;
        }
    }
}

// ===========================================================================
// Kernel 3: fused exp-softmax + PV + residual. 512 threads, 16 warps (2m x 8n).
//   Fragment loads via ldmatrix (24 LDSM vs 96 LDS per warp per chunk).
// ===========================================================================
constexpr int PV_AROW = 36;
constexpr int PV_AST  = 128 * PV_AROW;
constexpr int PV_BST  = 256 * PV_AROW;
constexpr int PV_SMEM = (3 * PV_AST + 4 * PV_BST + 128) * 4;   // 203,776 B
constexpr int NCH = Nq / 32;

__global__ __launch_bounds__(512, 1)
void pv_kernel(const float* __restrict__ gamma_p,
               const float* __restrict__ x, float* __restrict__ y) {
    extern __shared__ float sm[];
    float* Abuf = sm;
    float* Bbuf = sm + 3 * PV_AST;
    float* zsm  = sm + 3 * PV_AST + 4 * PV_BST;

    const int t = threadIdx.x;
    const int lane = t & 31, wid = t >> 5;
    const int wm = wid >> 3, wn = wid & 7;
    const int qbase = blockIdx.x * 128;
    const int b = blockIdx.y;
    const float* Pm  = g_s  + (size_t)b * Nq * Nq;
    const float* hTb = g_hT + (size_t)b * C * Nq;

    if (t < 128) zsm[t] = 0.f;

    const int tr  = t >> 3;
    const int tc4 = (t & 7) * 4;

    const int arow = (lane & 7) + ((lane >> 3) & 1) * 8;
    const int acol = (lane >> 4) * 4;
    const int brow = (lane >> 4) * 8 + (lane & 7);
    const int bcol = ((lane >> 3) & 1) * 4;

    float4 va[2], vb[2];
    float zp[2] = {0.f, 0.f};

    auto ldgA = [&](int chunk, float4* v) {
        const float* base = Pm + (size_t)(qbase + tr) * Nq + chunk * 32 + tc4;
        v[0] = *(const float4*)(base);
        v[1] = *(const float4*)(base + (size_t)64 * Nq);
    };
    auto expSts = [&](int chunk, const float4* v) {
        float* Ad = Abuf + (chunk % 3) * PV_AST;
        #pragma unroll
        for (int i = 0; i < 2; i++) {
            float4 p;
            p.x = __uint_as_float(f2tf32(__expf(v[i].x)));
            p.y = __uint_as_float(f2tf32(__expf(v[i].y)));
            p.z = __uint_as_float(f2tf32(__expf(v[i].z)));
            p.w = __uint_as_float(f2tf32(__expf(v[i].w)));
            zp[i] += (p.x + p.y) + (p.z + p.w);
            *(float4*)(Ad + (tr + 64 * i) * PV_AROW + tc4) = p;
        }
    };
    auto cpB = [&](int chunk) {
        float* Bd = Bbuf + (chunk & 3) * PV_BST;
        #pragma unroll
        for (int i = 0; i < 4; i++) {
            int idx = t + i * 512;
            int r = idx >> 3, c4 = (idx & 7) * 4;
            cp16(smem_u32(Bd + r * PV_AROW + c4),
                 hTb + (size_t)r * Nq + chunk * 32 + c4);
        }
        cp_commit();
    };

    cpB(0); cpB(1); cpB(2);
    ldgA(0, va);
    expSts(0, va);
    ldgA(1, va);

    float acc[4][4][4] = {};

    for (int c = 0; c < NCH; c++) {
        if (c + 1 < NCH) expSts(c + 1, va);
        if (c + 2 < NCH) ldgA(c + 2, vb);

        int pend = NCH - 1 - c;
        if (pend >= 2)      asm volatile("cp.async.wait_group 2;" ::: "memory");
        else if (pend == 1) asm volatile("cp.async.wait_group 1;" ::: "memory");
        else                asm volatile("cp.async.wait_group 0;" ::: "memory");
        __syncthreads();

        if (c + 3 < NCH) cpB(c + 3);

        const uint32_t AsbU = smem_u32(Abuf + (c % 3) * PV_AST);
        const uint32_t BsbU = smem_u32(Bbuf + (c & 3) * PV_BST);
        #pragma unroll
        for (int ks = 0; ks < 4; ks++) {
            uint32_t af[4][4];
            #pragma unroll
            for (int mt = 0; mt < 4; mt++)
                ldsm4(af[mt], AsbU + ((wm * 64 + mt * 16 + arow) * PV_AROW + ks * 8 + acol) * 4);
            #pragma unroll
            for (int j = 0; j < 2; j++) {
                uint32_t bf[4];
                ldsm4(bf, BsbU + ((wn * 32 + j * 16 + brow) * PV_AROW + ks * 8 + bcol) * 4);
                #pragma unroll
                for (int mt = 0; mt < 4; mt++) {
                    mma_tf32(acc[mt][2 * j + 0], af[mt], bf + 0);
                    mma_tf32(acc[mt][2 * j + 1], af[mt], bf + 2);
                }
            }
        }

        va[0] = vb[0]; va[1] = vb[1];
    }

    __syncthreads();
    atomicAdd(&zsm[tr], zp[0]);
    atomicAdd(&zsm[tr + 64], zp[1]);
    __syncthreads();

    const float gam = __ldg(gamma_p);
    #pragma unroll
    for (int mt = 0; mt < 4; mt++) {
        int row0 = wm * 64 + mt * 16 + (lane >> 2);
        float sc0 = gam / zsm[row0];
        float sc1 = gam / zsm[row0 + 8];
        #pragma unroll
        for (int nt = 0; nt < 4; nt++) {
            int col = wn * 32 + nt * 8 + 2 * (lane & 3);
            size_t base = ((size_t)b * Nq + qbase + row0) * C + col;
            float2 x0 = *(const float2*)(x + base);
            float2 o0;
            o0.x = sc0 * acc[mt][nt][0] + x0.x;
            o0.y = sc0 * acc[mt][nt][1] + x0.y;
            *(float2*)(y + base) = o0;
            size_t base2 = base + 8 * (size_t)C;
            float2 x1 = *(const float2*)(x + base2);
            float2 o1;
            o1.x = sc1 * acc[mt][nt][2] + x1.x;
            o1.y = sc1 * acc[mt][nt][3] + x1.y;
            *(float2*)(y + base2) = o1;
        }
    }
}

// ===========================================================================
extern "C" void kernel_launch(void* const* d_in, const int* in_sizes, int n_in,
                              void* d_out, int out_size) {
    (void)in_sizes; (void)n_in; (void)out_size;
    const float* x     = (const float*)d_in[0];
    const float* Wf    = (const float*)d_in[1];
    const float* bf    = (const float*)d_in[2];
    const float* Wg    = (const float*)d_in[3];
    const float* bg    = (const float*)d_in[4];
    const float* Wh    = (const float*)d_in[5];
    const float* bh    = (const float*)d_in[6];
    const float* gamma = (const float*)d_in[7];
    float* y = (float*)d_out;

    cudaFuncSetAttribute(proj_kernel, cudaFuncAttributeMaxDynamicSharedMemorySize, PJ_SMEM);
    cudaFuncSetAttribute(score_kernel, cudaFuncAttributeMaxDynamicSharedMemorySize, SC_SMEM);
    cudaFuncSetAttribute(pv_kernel, cudaFuncAttributeMaxDynamicSharedMemorySize, PV_SMEM);

    wtrans_kernel<<<320, 256>>>(Wf, Wg, Wh);
    proj_kernel<<<(Bb * Nq) / 64, 256, PJ_SMEM>>>(x, bf, bg, bh);
    score_kernel<<<dim3(Nq / 128, Nq / 128, Bb), 256, SC_SMEM>>>();
    pv_kernel<<<dim3(Nq / 128, Bb), 512, PV_SMEM>>>(gamma, x, y);
}